// round 14
// baseline (speedup 1.0000x reference)
#include <cuda_runtime.h>
#include <math.h>

#define EPSF 1e-8f
#define MAXV 16
#define NBLK 4096

__device__ float g_partials[NBLK];
__device__ unsigned int g_count = 0;

struct Box2D {
    float X[4], Y[4];
    float area;
    float zmin, zmax, vol;
};

__device__ __forceinline__ Box2D decode_box(const float* __restrict__ d) {
    float d0 = d[0], d1 = d[1], d2 = d[2], d3 = d[3], d4 = d[4], d5 = d[5];
    float th = d[6];
    float w = d0 + d3, l = d1 + d4, h = d2 + d5;
    float ox = 0.5f * (d3 - d0), oy = 0.5f * (d4 - d1), oz = 0.5f * (d5 - d2);
    float c = __cosf(th), s = __sinf(th);
    float cx = ox * c - oy * s;
    float cy = ox * s + oy * c;
    Box2D b;
    const float xs[4] = {0.5f, -0.5f, -0.5f, 0.5f};
    const float ys[4] = {0.5f, 0.5f, -0.5f, -0.5f};
#pragma unroll
    for (int k = 0; k < 4; k++) {
        float x4 = xs[k] * w, y4 = ys[k] * l;
        b.X[k] = x4 * c - y4 * s + cx;
        b.Y[k] = x4 * s + y4 * c + cy;
    }
    b.area = w * l;
    b.zmin = oz - 0.5f * h;
    b.zmax = oz + 0.5f * h;
    b.vol  = w * l * h;
    return b;
}

// Division-free reference containment test (verified rel_err 0.0)
__device__ __forceinline__ void in_box_mask(const Box2D& P, const Box2D& Q, bool* m) {
    const float tol = 1e-6f;
    float ax = Q.X[0], ay = Q.Y[0];
    float abx = Q.X[1] - ax, aby = Q.Y[1] - ay;
    float adx = Q.X[3] - ax, ady = Q.Y[3] - ay;
    float ab2 = abx * abx + aby * aby;
    float ad2 = adx * adx + ady * ady;
    float ab_lo = -tol * ab2, ab_hi = (1.0f + tol) * ab2;
    float ad_lo = -tol * ad2, ad_hi = (1.0f + tol) * ad2;
#pragma unroll
    for (int i = 0; i < 4; i++) {
        float amx = P.X[i] - ax, amy = P.Y[i] - ay;
        float dab = abx * amx + aby * amy;
        float dad = adx * amx + ady * amy;
        m[i] = (dab > ab_lo) & (dab < ab_hi) & (dad > ad_lo) & (dad < ad_hi);
    }
}

// Monotone surrogate of atan2f (verified): same sort order.
__device__ __forceinline__ float pangle(float x, float y) {
    float d = fabsf(x) + fabsf(y);
    float r = __fdividef(x, fmaxf(d, 1e-35f));
    return (__float_as_int(y) < 0) ? (r - 1.0f) : (1.0f - r);
}

// Ordered-float encoding (verified): monotone, -0 == +0.
__device__ __forceinline__ unsigned int fkey(float f) {
    unsigned int b = __float_as_uint(f);
    if (b == 0x80000000u) b = 0u;
    return (b & 0x80000000u) ? ~b : (b | 0x80000000u);
}

__global__ void __launch_bounds__(256)
riou_kernel(const float* __restrict__ pred,
            const float* __restrict__ target,
            const float* __restrict__ weight,
            float* __restrict__ out,
            int n, int nb) {
    __shared__ float s_p[256 * 7];
    __shared__ float s_t[256 * 7];
    const int tid = threadIdx.x;
    float acc = 0.0f;

    for (int ib = blockIdx.x; ib * 256 < n; ib += gridDim.x) {
        {
            size_t base = (size_t)ib * 256 * 7;
            size_t total = (size_t)n * 7;
#pragma unroll
            for (int j = 0; j < 7; j++) {
                size_t g = base + (size_t)j * 256 + tid;
                bool ok = g < total;
                s_p[j * 256 + tid] = ok ? pred[g]   : 0.0f;
                s_t[j * 256 + tid] = ok ? target[g] : 0.0f;
            }
        }
        __syncthreads();

        int i = ib * 256 + tid;
        if (i < n) {
            Box2D b1 = decode_box(s_p + tid * 7);
            Box2D b2 = decode_box(s_t + tid * 7);

            float zo = fminf(b1.zmax, b2.zmax) - fmaxf(b1.zmin, b2.zmin);
            zo = fmaxf(zo, 0.0f);

            float inter = 0.0f;
            if (zo > 0.0f) {
                float2 vtx[MAXV];
                unsigned long long key[MAXV];
                int nv = 0;
                float sx = 0.0f, sy = 0.0f;

                bool m12[4], m21[4];
                in_box_mask(b1, b2, m12);
                in_box_mask(b2, b1, m21);
#pragma unroll
                for (int k = 0; k < 4; k++)
                    if (m12[k]) { vtx[nv] = make_float2(b1.X[k], b1.Y[k]); sx += b1.X[k]; sy += b1.Y[k]; nv++; }
#pragma unroll
                for (int k = 0; k < 4; k++)
                    if (m21[k]) { vtx[nv] = make_float2(b2.X[k], b2.Y[k]); sx += b2.X[k]; sy += b2.Y[k]; nv++; }

                float fxv[4], fyv[4];
#pragma unroll
                for (int b = 0; b < 4; b++) {
                    fxv[b] = b2.X[(b + 1) & 3] - b2.X[b];
                    fyv[b] = b2.Y[(b + 1) & 3] - b2.Y[b];
                }

                // 16 edge crossings, division-free masks (verified)
#pragma unroll
                for (int a = 0; a < 4; a++) {
                    float x1 = b1.X[a], y1 = b1.Y[a];
                    float ex = b1.X[(a + 1) & 3] - x1;
                    float ey = b1.Y[(a + 1) & 3] - y1;
#pragma unroll
                    for (int b = 0; b < 4; b++) {
                        float x3 = b2.X[b], y3 = b2.Y[b];
                        float fx = fxv[b], fy = fyv[b];
                        float rx = y1 - y3, ry = x1 - x3;
                        float num = fy * ex - fx * ey;
                        float dt  = fx * rx - fy * ry;
                        float du  = ex * rx - ey * ry;
                        bool ok = (dt * num > 0.0f) && ((dt - num) * num < 0.0f) &&
                                  (du * num < 0.0f) && ((du + num) * num > 0.0f) &&
                                  (nv < MAXV);
                        if (ok) {
                            float t2 = __fdividef(dt, num + EPSF);
                            float px = x1 + t2 * ex;
                            float py = y1 + t2 * ey;
                            vtx[nv] = make_float2(px, py);
                            sx += px; sy += py;
                            nv++;
                        }
                    }
                }

                if (nv >= 3) {
                    float inv = __fdividef(1.0f, (float)nv);
                    float mx = sx * inv, my = sy * inv;

                    // unique 64-bit stable keys (verified)
                    for (int k = 0; k < nv; k++) {
                        float2 v = vtx[k];
                        float ang = pangle(v.x - mx, v.y - my);
                        key[k] = ((unsigned long long)fkey(ang) << 32) | (unsigned int)k;
                    }

                    // branch-free rank ordering: rank_j = #{k: key_k < key_j}
                    // keys unique -> exact permutation, identical to stable sort.
                    int pos[MAXV];
                    for (int j = 0; j < nv; j++) {
                        unsigned long long kj = key[j];
                        int r = 0;
                        for (int k = 0; k < nv; k++)
                            r += (key[k] < kj);
                        pos[r] = j;
                    }

                    // shoelace over sorted order
                    float cs = 0.0f;
                    float2 first = make_float2(0.f, 0.f), prev = make_float2(0.f, 0.f);
                    for (int k = 0; k < nv; k++) {
                        float2 v = vtx[pos[k]];
                        v.x -= mx; v.y -= my;
                        if (k == 0) first = v;
                        else cs += prev.x * v.y - prev.y * v.x;
                        prev = v;
                    }
                    cs += prev.x * first.y - prev.y * first.x;
                    inter = 0.5f * fabsf(cs);
                }
            }

            float u2 = b1.area + b2.area - inter;
            float iou2d = __fdividef(inter, u2);
            float inter3 = iou2d * u2 * zo;
            float u3 = b1.vol + b2.vol - inter3;
            float r = __fdividef(inter3 + 1.0f, u3 + 1.0f);
            acc += -__logf(r) * weight[i];
        }
        __syncthreads();
    }

    // ---- intra-block reduction (verbatim, verified) ----
    __shared__ float warp_s[8];
#pragma unroll
    for (int o = 16; o > 0; o >>= 1)
        acc += __shfl_down_sync(0xffffffffu, acc, o);
    int lane = threadIdx.x & 31, wid = threadIdx.x >> 5;
    if (lane == 0) warp_s[wid] = acc;
    __syncthreads();
    if (wid == 0) {
        float v = (lane < 8) ? warp_s[lane] : 0.0f;
#pragma unroll
        for (int o = 4; o > 0; o >>= 1)
            v += __shfl_down_sync(0xffffffffu, v, o);
        if (lane == 0) __stcg(&g_partials[blockIdx.x], v);
    }

    // ---- last-block-done final reduction (verbatim, verified) ----
    __shared__ bool is_last;
    __threadfence();
    if (threadIdx.x == 0) {
        unsigned int c = atomicAdd(&g_count, 1u);
        is_last = (c == (unsigned int)(nb - 1));
    }
    __syncthreads();
    if (is_last) {
        float s = 0.0f;
        for (int k = threadIdx.x; k < nb; k += 256)
            s += __ldcg(&g_partials[k]);
#pragma unroll
        for (int o = 16; o > 0; o >>= 1)
            s += __shfl_down_sync(0xffffffffu, s, o);
        if (lane == 0) warp_s[wid] = s;
        __syncthreads();
        if (wid == 0) {
            float v = (lane < 8) ? warp_s[lane] : 0.0f;
#pragma unroll
            for (int o = 4; o > 0; o >>= 1)
                v += __shfl_down_sync(0xffffffffu, v, o);
            if (lane == 0) {
                out[0] = v;
                g_count = 0;
            }
        }
    }
}

extern "C" void kernel_launch(void* const* d_in, const int* in_sizes, int n_in,
                              void* d_out, int out_size) {
    const float* pred   = (const float*)d_in[0];
    const float* target = (const float*)d_in[1];
    const float* weight = (const float*)d_in[2];
    float* out = (float*)d_out;

    int n = (n_in >= 3) ? in_sizes[2] : in_sizes[0] / 7;
    int nb = (n + 255) / 256;
    if (nb > NBLK) nb = NBLK;

    riou_kernel<<<nb, 256>>>(pred, target, weight, out, n, nb);
}

// round 15
// speedup vs baseline: 1.1430x; 1.1430x over previous
#include <cuda_runtime.h>
#include <math.h>

#define EPSF 1e-8f
#define MAXV 16
#define NBLK 4096

__device__ float g_partials[NBLK];
__device__ unsigned int g_count = 0;

struct Box2D {
    float X[4], Y[4];
    float area;
    float zmin, zmax, vol;
};

__device__ __forceinline__ Box2D decode_box(const float* __restrict__ d) {
    float d0 = d[0], d1 = d[1], d2 = d[2], d3 = d[3], d4 = d[4], d5 = d[5];
    float th = d[6];
    float w = d0 + d3, l = d1 + d4, h = d2 + d5;
    float ox = 0.5f * (d3 - d0), oy = 0.5f * (d4 - d1), oz = 0.5f * (d5 - d2);
    float c = __cosf(th), s = __sinf(th);
    float cx = ox * c - oy * s;
    float cy = ox * s + oy * c;
    Box2D b;
    const float xs[4] = {0.5f, -0.5f, -0.5f, 0.5f};
    const float ys[4] = {0.5f, 0.5f, -0.5f, -0.5f};
#pragma unroll
    for (int k = 0; k < 4; k++) {
        float x4 = xs[k] * w, y4 = ys[k] * l;
        b.X[k] = x4 * c - y4 * s + cx;
        b.Y[k] = x4 * s + y4 * c + cy;
    }
    b.area = w * l;
    b.zmin = oz - 0.5f * h;
    b.zmax = oz + 0.5f * h;
    b.vol  = w * l * h;
    return b;
}

// Division-free reference containment test (verified rel_err 0.0)
__device__ __forceinline__ void in_box_mask(const Box2D& P, const Box2D& Q, bool* m) {
    const float tol = 1e-6f;
    float ax = Q.X[0], ay = Q.Y[0];
    float abx = Q.X[1] - ax, aby = Q.Y[1] - ay;
    float adx = Q.X[3] - ax, ady = Q.Y[3] - ay;
    float ab2 = abx * abx + aby * aby;
    float ad2 = adx * adx + ady * ady;
    float ab_lo = -tol * ab2, ab_hi = (1.0f + tol) * ab2;
    float ad_lo = -tol * ad2, ad_hi = (1.0f + tol) * ad2;
#pragma unroll
    for (int i = 0; i < 4; i++) {
        float amx = P.X[i] - ax, amy = P.Y[i] - ay;
        float dab = abx * amx + aby * amy;
        float dad = adx * amx + ady * amy;
        m[i] = (dab > ab_lo) & (dab < ab_hi) & (dad > ad_lo) & (dad < ad_hi);
    }
}

// Monotone surrogate of atan2f (verified): same sort order.
__device__ __forceinline__ float pangle(float x, float y) {
    float d = fabsf(x) + fabsf(y);
    float r = __fdividef(x, fmaxf(d, 1e-35f));
    return (__float_as_int(y) < 0) ? (r - 1.0f) : (1.0f - r);
}

// Ordered-float encoding (verified): monotone, -0 == +0.
__device__ __forceinline__ unsigned int fkey(float f) {
    unsigned int b = __float_as_uint(f);
    if (b == 0x80000000u) b = 0u;
    return (b & 0x80000000u) ? ~b : (b | 0x80000000u);
}

// branch-free compare-exchange on u64 keys
#define CE(a, b) { \
    unsigned long long _ka = key[a], _kb = key[b]; \
    unsigned long long _lo = (_ka < _kb) ? _ka : _kb; \
    unsigned long long _hi = (_ka < _kb) ? _kb : _ka; \
    key[a] = _lo; key[b] = _hi; }

__global__ void __launch_bounds__(256)
riou_kernel(const float* __restrict__ pred,
            const float* __restrict__ target,
            const float* __restrict__ weight,
            float* __restrict__ out,
            int n, int nb) {
    __shared__ float s_p[256 * 7];
    __shared__ float s_t[256 * 7];
    const int tid = threadIdx.x;
    float acc = 0.0f;

    for (int ib = blockIdx.x; ib * 256 < n; ib += gridDim.x) {
        {
            size_t base = (size_t)ib * 256 * 7;
            size_t total = (size_t)n * 7;
#pragma unroll
            for (int j = 0; j < 7; j++) {
                size_t g = base + (size_t)j * 256 + tid;
                bool ok = g < total;
                s_p[j * 256 + tid] = ok ? pred[g]   : 0.0f;
                s_t[j * 256 + tid] = ok ? target[g] : 0.0f;
            }
        }
        __syncthreads();

        int i = ib * 256 + tid;
        if (i < n) {
            Box2D b1 = decode_box(s_p + tid * 7);
            Box2D b2 = decode_box(s_t + tid * 7);

            float zo = fminf(b1.zmax, b2.zmax) - fmaxf(b1.zmin, b2.zmin);
            zo = fmaxf(zo, 0.0f);

            float inter = 0.0f;
            if (zo > 0.0f) {
                float2 vtx[MAXV];
                int nv = 0;
                float sx = 0.0f, sy = 0.0f;

                bool m12[4], m21[4];
                in_box_mask(b1, b2, m12);
                in_box_mask(b2, b1, m21);
#pragma unroll
                for (int k = 0; k < 4; k++)
                    if (m12[k]) { vtx[nv] = make_float2(b1.X[k], b1.Y[k]); sx += b1.X[k]; sy += b1.Y[k]; nv++; }
#pragma unroll
                for (int k = 0; k < 4; k++)
                    if (m21[k]) { vtx[nv] = make_float2(b2.X[k], b2.Y[k]); sx += b2.X[k]; sy += b2.Y[k]; nv++; }

                float fxv[4], fyv[4];
#pragma unroll
                for (int b = 0; b < 4; b++) {
                    fxv[b] = b2.X[(b + 1) & 3] - b2.X[b];
                    fyv[b] = b2.Y[(b + 1) & 3] - b2.Y[b];
                }

                // 16 edge crossings, division-free masks (verified)
#pragma unroll
                for (int a = 0; a < 4; a++) {
                    float x1 = b1.X[a], y1 = b1.Y[a];
                    float ex = b1.X[(a + 1) & 3] - x1;
                    float ey = b1.Y[(a + 1) & 3] - y1;
#pragma unroll
                    for (int b = 0; b < 4; b++) {
                        float x3 = b2.X[b], y3 = b2.Y[b];
                        float fx = fxv[b], fy = fyv[b];
                        float rx = y1 - y3, ry = x1 - x3;
                        float num = fy * ex - fx * ey;
                        float dt  = fx * rx - fy * ry;
                        float du  = ex * rx - ey * ry;
                        bool ok = (dt * num > 0.0f) && ((dt - num) * num < 0.0f) &&
                                  (du * num < 0.0f) && ((du + num) * num > 0.0f) &&
                                  (nv < MAXV);
                        if (ok) {
                            float t2 = __fdividef(dt, num + EPSF);
                            float px = x1 + t2 * ex;
                            float py = y1 + t2 * ey;
                            vtx[nv] = make_float2(px, py);
                            sx += px; sy += py;
                            nv++;
                        }
                    }
                }

                if (nv >= 3) {
                    float inv = __fdividef(1.0f, (float)nv);
                    float mx = sx * inv, my = sy * inv;

                    // ---- register-resident key array: static indices only ----
                    unsigned long long key[16];
#pragma unroll
                    for (int k = 0; k < 16; k++) {
                        if (k < nv) {
                            float2 v = vtx[k];                    // static-index LDL, independent
                            float ang = pangle(v.x - mx, v.y - my);
                            key[k] = ((unsigned long long)fkey(ang) << 32) | (unsigned int)k;
                        } else {
                            key[k] = (0xFFFFFFFFull << 32) | (unsigned int)k;  // +INF: sorts last
                        }
                    }

                    // ---- Batcher odd-even merge sort network, n=16, 63 CE ----
                    CE(0,1) CE(2,3) CE(4,5) CE(6,7) CE(8,9) CE(10,11) CE(12,13) CE(14,15)
                    CE(0,2) CE(1,3) CE(4,6) CE(5,7) CE(8,10) CE(9,11) CE(12,14) CE(13,15)
                    CE(1,2) CE(5,6) CE(9,10) CE(13,14)
                    CE(0,4) CE(1,5) CE(2,6) CE(3,7) CE(8,12) CE(9,13) CE(10,14) CE(11,15)
                    CE(2,4) CE(3,5) CE(10,12) CE(11,13)
                    CE(1,2) CE(3,4) CE(5,6) CE(9,10) CE(11,12) CE(13,14)
                    CE(0,8) CE(1,9) CE(2,10) CE(3,11) CE(4,12) CE(5,13) CE(6,14) CE(7,15)
                    CE(4,8) CE(5,9) CE(6,10) CE(7,11)
                    CE(2,4) CE(3,5) CE(6,8) CE(7,9) CE(10,12) CE(11,13)
                    CE(1,2) CE(3,4) CE(5,6) CE(7,8) CE(9,10) CE(11,12) CE(13,14)

                    // ---- unrolled shoelace over sorted valid slots ----
                    float cs = 0.0f;
                    float fx0 = 0.0f, fy0 = 0.0f, pvx = 0.0f, pvy = 0.0f;
#pragma unroll
                    for (int k = 0; k < 16; k++) {
                        if (k < nv) {
                            int id = (int)(key[k] & 0xFFu);       // static key read
                            float2 v = vtx[id];                   // gather (independent LDL)
                            float vx = v.x - mx, vy = v.y - my;
                            if (k == 0) { fx0 = vx; fy0 = vy; }
                            else cs += pvx * vy - pvy * vx;
                            pvx = vx; pvy = vy;
                        }
                    }
                    cs += pvx * fy0 - pvy * fx0;
                    inter = 0.5f * fabsf(cs);
                }
            }

            float u2 = b1.area + b2.area - inter;
            float iou2d = __fdividef(inter, u2);
            float inter3 = iou2d * u2 * zo;
            float u3 = b1.vol + b2.vol - inter3;
            float r = __fdividef(inter3 + 1.0f, u3 + 1.0f);
            acc += -__logf(r) * weight[i];
        }
        __syncthreads();
    }

    // ---- intra-block reduction (verbatim, verified) ----
    __shared__ float warp_s[8];
#pragma unroll
    for (int o = 16; o > 0; o >>= 1)
        acc += __shfl_down_sync(0xffffffffu, acc, o);
    int lane = threadIdx.x & 31, wid = threadIdx.x >> 5;
    if (lane == 0) warp_s[wid] = acc;
    __syncthreads();
    if (wid == 0) {
        float v = (lane < 8) ? warp_s[lane] : 0.0f;
#pragma unroll
        for (int o = 4; o > 0; o >>= 1)
            v += __shfl_down_sync(0xffffffffu, v, o);
        if (lane == 0) __stcg(&g_partials[blockIdx.x], v);
    }

    // ---- last-block-done final reduction (verbatim, verified) ----
    __shared__ bool is_last;
    __threadfence();
    if (threadIdx.x == 0) {
        unsigned int c = atomicAdd(&g_count, 1u);
        is_last = (c == (unsigned int)(nb - 1));
    }
    __syncthreads();
    if (is_last) {
        float s = 0.0f;
        for (int k = threadIdx.x; k < nb; k += 256)
            s += __ldcg(&g_partials[k]);
#pragma unroll
        for (int o = 16; o > 0; o >>= 1)
            s += __shfl_down_sync(0xffffffffu, s, o);
        if (lane == 0) warp_s[wid] = s;
        __syncthreads();
        if (wid == 0) {
            float v = (lane < 8) ? warp_s[lane] : 0.0f;
#pragma unroll
            for (int o = 4; o > 0; o >>= 1)
                v += __shfl_down_sync(0xffffffffu, v, o);
            if (lane == 0) {
                out[0] = v;
                g_count = 0;
            }
        }
    }
}

extern "C" void kernel_launch(void* const* d_in, const int* in_sizes, int n_in,
                              void* d_out, int out_size) {
    const float* pred   = (const float*)d_in[0];
    const float* target = (const float*)d_in[1];
    const float* weight = (const float*)d_in[2];
    float* out = (float*)d_out;

    int n = (n_in >= 3) ? in_sizes[2] : in_sizes[0] / 7;
    int nb = (n + 255) / 256;
    if (nb > NBLK) nb = NBLK;

    riou_kernel<<<nb, 256>>>(pred, target, weight, out, n, nb);
}